// round 1
// baseline (speedup 1.0000x reference)
#include <cuda_runtime.h>

#define CO 256
#define CI 256
#define SS 57      // effective max dilated kernel length
#define NW 12      // number of (k,d) combos
#define ROLL 29    // (SS+1)/2
#define HEAD 28    // SS - ROLL

struct WPtrs { const float* w[NW]; };

// KD order = product(KS=[3,5,7,9], DS=[1,3,7])
__device__ __constant__ const int c_K[NW] = {3,3,3, 5,5,5, 7,7,7, 9,9,9};
__device__ __constant__ const int c_D[NW] = {1,3,7, 1,3,7, 1,3,7, 1,3,7};

__global__ void __launch_bounds__(256)
multiconv_perm_kernel(WPtrs wp,
                      const float* __restrict__ alpha,
                      const float* __restrict__ gum,
                      float* __restrict__ out,
                      int N) {
    __shared__ float scoef[NW];
    __shared__ float sacc[SS];

    const int tid = threadIdx.x;
    const int row = blockIdx.x;          // co*CI + ci, 0..65535

    // --- coef = softmax(alpha + gumbels)  (log_softmax drops out: shift-invariant) ---
    if (tid == 0) {
        float l[NW];
        float m = -1e30f;
        #pragma unroll
        for (int i = 0; i < NW; i++) {
            l[i] = alpha[i] + gum[i];
            m = fmaxf(m, l[i]);
        }
        float s = 0.0f;
        #pragma unroll
        for (int i = 0; i < NW; i++) {
            l[i] = expf(l[i] - m);
            s += l[i];
        }
        const float inv = 1.0f / s;
        #pragma unroll
        for (int i = 0; i < NW; i++) scoef[i] = l[i] * inv;
    }
    __syncthreads();

    // --- acc[s] = sum_i coef[i] * dilate(w_i, d)[padded to SS] at position s ---
    if (tid < SS) {
        float a = 0.0f;
        #pragma unroll
        for (int i = 0; i < NW; i++) {
            const int k = c_K[i];
            const int d = c_D[i];
            const int L = d * (k - 1) + 1;
            const int pl = (SS - L) >> 1;      // left pad = (S-L)//2
            const int t = tid - pl;
            if (t >= 0 && t < L && (t % d) == 0) {
                a += scoef[i] * wp.w[i][row * k + t / d];
            }
        }
        sacc[tid] = a;
    }
    __syncthreads();

    // --- flip + roll scatter:
    //     out[j] = acc[28-j]        for j in [0,28]
    //     out[j] = acc[N+28-j]      for j in [N-28, N-1]
    //     out[j] = 0                otherwise
    const size_t base = (size_t)row * (size_t)N;
    const int lo = HEAD;        // j <= 28 -> head values
    const int hi = N - HEAD;    // j >= N-28 -> tail values

    if ((N & 3) == 0) {
        const int stride = blockDim.x * 4;
        for (int j0 = tid * 4; j0 < N; j0 += stride) {
            float4 v;
            {
                int j = j0;
                v.x = (j <= lo) ? sacc[HEAD - j] : ((j >= hi) ? sacc[N + HEAD - j] : 0.0f);
                j = j0 + 1;
                v.y = (j <= lo) ? sacc[HEAD - j] : ((j >= hi) ? sacc[N + HEAD - j] : 0.0f);
                j = j0 + 2;
                v.z = (j <= lo) ? sacc[HEAD - j] : ((j >= hi) ? sacc[N + HEAD - j] : 0.0f);
                j = j0 + 3;
                v.w = (j <= lo) ? sacc[HEAD - j] : ((j >= hi) ? sacc[N + HEAD - j] : 0.0f);
            }
            *reinterpret_cast<float4*>(out + base + j0) = v;
        }
    } else {
        for (int j = tid; j < N; j += blockDim.x) {
            out[base + j] = (j <= lo) ? sacc[HEAD - j]
                          : ((j >= hi) ? sacc[N + HEAD - j] : 0.0f);
        }
    }
}

extern "C" void kernel_launch(void* const* d_in, const int* in_sizes, int n_in,
                              void* d_out, int out_size) {
    WPtrs wp;
    for (int i = 0; i < NW; i++) wp.w[i] = (const float*)d_in[i];
    const float* alpha = (const float*)d_in[12];
    const float* gum   = (const float*)d_in[13];
    // input_size lives on-device (d_in[14]); recover it host-side from out_size
    // (out_size = CO*CI*input_size) to stay sync-free / graph-capturable.
    const int N = out_size / (CO * CI);

    float* out = (float*)d_out;
    multiconv_perm_kernel<<<CO * CI, 256>>>(wp, alpha, gum, out, N);
}

// round 2
// speedup vs baseline: 1.7826x; 1.7826x over previous
#include <cuda_runtime.h>

#define CO 256
#define CI 256
#define SS 57      // effective max dilated kernel length
#define NW 12      // number of (k,d) combos
#define ROLL 29    // (SS+1)/2
#define HEAD 28    // SS - ROLL

struct WPtrs { const float* w[NW]; };

// KD order = product(KS=[3,5,7,9], DS=[1,3,7])
__device__ __constant__ const int c_K[NW] = {3,3,3, 5,5,5, 7,7,7, 9,9,9};
__device__ __constant__ const int c_D[NW] = {1,3,7, 1,3,7, 1,3,7, 1,3,7};

// coef = softmax(alpha + gumbels), computed ONCE per launch
__device__ float g_coef[NW];

__global__ void coef_kernel(const float* __restrict__ alpha,
                            const float* __restrict__ gum) {
    if (threadIdx.x == 0) {
        float l[NW];
        float m = -1e30f;
        #pragma unroll
        for (int i = 0; i < NW; i++) {
            l[i] = alpha[i] + gum[i];
            m = fmaxf(m, l[i]);
        }
        float s = 0.0f;
        #pragma unroll
        for (int i = 0; i < NW; i++) {
            l[i] = expf(l[i] - m);
            s += l[i];
        }
        const float inv = 1.0f / s;
        #pragma unroll
        for (int i = 0; i < NW; i++) g_coef[i] = l[i] * inv;
    }
}

// Per row (co,ci):
//   out[j] = sacc[HEAD-j]      for j in [0, HEAD]        (head)
//   out[j] = sacc[N+HEAD-j]    for j in [N-HEAD, N-1]    (tail)
//   out[j] = 0                 otherwise                 (interior, ~94% of row)
//
// Slot remap (float4 slots, N%4==0, N>=64):
//   slot 0..7   -> head   j0 = 4*slot
//   slot 8..14  -> tail   j0 = (N-HEAD) + 4*(slot-8)     (N-HEAD ≡ 0 mod 4)
//   slot 15+    -> zero   j0 = 32 + 4*(slot-15)          (covers [32, N-36])
__global__ void __launch_bounds__(256)
multiconv_perm_kernel(WPtrs wp, float* __restrict__ out, int N) {
    __shared__ float sacc[SS];

    const int tid = threadIdx.x;
    const int row = blockIdx.x;
    const size_t base = (size_t)row * (size_t)N;

    // Only warps 0-1 build sacc; only warp 0 reads it. Others never sync.
    if (tid < 64) {
        if (tid < SS) {
            float a = 0.0f;
            #pragma unroll
            for (int i = 0; i < NW; i++) {
                const int k = c_K[i];
                const int d = c_D[i];
                const int L = d * (k - 1) + 1;
                const int pl = (SS - L) >> 1;      // left pad
                const int t = tid - pl;
                if (t >= 0 && t < L && (t % d) == 0) {
                    a += g_coef[i] * wp.w[i][row * k + t / d];
                }
            }
            sacc[tid] = a;
        }
        asm volatile("bar.sync 1, 64;" ::: "memory");
    }

    const int nslots = N >> 2;
    const int hi = N - HEAD;            // first tail j

    for (int s = tid; s < nslots; s += 256) {
        float4 v = make_float4(0.f, 0.f, 0.f, 0.f);
        int j0;
        if (s >= 15) {                  // interior: pure zero store (241/256 slots)
            j0 = 32 + ((s - 15) << 2);
        } else if (s < 8) {             // head
            j0 = s << 2;
            v.x = sacc[HEAD - j0];
            v.y = (j0 + 1 <= HEAD) ? sacc[HEAD - j0 - 1] : 0.f;
            v.z = (j0 + 2 <= HEAD) ? sacc[HEAD - j0 - 2] : 0.f;
            v.w = (j0 + 3 <= HEAD) ? sacc[HEAD - j0 - 3] : 0.f;
        } else {                        // tail (s in [8,14])
            j0 = hi + ((s - 8) << 2);
            v.x = sacc[N + HEAD - j0];
            v.y = sacc[N + HEAD - j0 - 1];
            v.z = sacc[N + HEAD - j0 - 2];
            v.w = sacc[N + HEAD - j0 - 3];
        }
        *reinterpret_cast<float4*>(out + base + j0) = v;
    }
}

// Fallback for N not multiple of 4 or N < 64 (not expected: N=1024)
__global__ void __launch_bounds__(256)
multiconv_perm_fallback(WPtrs wp, float* __restrict__ out, int N) {
    __shared__ float sacc[SS];
    const int tid = threadIdx.x;
    const int row = blockIdx.x;
    if (tid < SS) {
        float a = 0.0f;
        #pragma unroll
        for (int i = 0; i < NW; i++) {
            const int k = c_K[i];
            const int d = c_D[i];
            const int L = d * (k - 1) + 1;
            const int pl = (SS - L) >> 1;
            const int t = tid - pl;
            if (t >= 0 && t < L && (t % d) == 0)
                a += g_coef[i] * wp.w[i][row * k + t / d];
        }
        sacc[tid] = a;
    }
    __syncthreads();
    const size_t base = (size_t)row * (size_t)N;
    const int hi = N - HEAD;
    for (int j = tid; j < N; j += 256) {
        out[base + j] = (j <= HEAD) ? sacc[HEAD - j]
                      : ((j >= hi) ? sacc[N + HEAD - j] : 0.0f);
    }
}

extern "C" void kernel_launch(void* const* d_in, const int* in_sizes, int n_in,
                              void* d_out, int out_size) {
    WPtrs wp;
    for (int i = 0; i < NW; i++) wp.w[i] = (const float*)d_in[i];
    const float* alpha = (const float*)d_in[12];
    const float* gum   = (const float*)d_in[13];
    const int N = out_size / (CO * CI);   // input_size, recovered host-side

    float* out = (float*)d_out;
    coef_kernel<<<1, 32>>>(alpha, gum);
    if ((N & 3) == 0 && N >= 64) {
        multiconv_perm_kernel<<<CO * CI, 256>>>(wp, out, N);
    } else {
        multiconv_perm_fallback<<<CO * CI, 256>>>(wp, out, N);
    }
}